// round 4
// baseline (speedup 1.0000x reference)
#include <cuda_runtime.h>
#include <cstddef>

#define FULL_MASK 0xFFFFFFFFu

// One warp handles one row of 1024 floats.
// Thread owns 8 float4 = 32 elements: i = 128*k + 4*lane + b.
//   bits {0,1}  : inside float4           -> 2 intra-vector stages
//   bits {7,8,9}: register index k        -> 3 register-pair stages
//   bits {2..6} : lane index              -> 5 shfl_xor stages (masks 1..16)
__global__ void __launch_bounds__(256, 4)
fwht1024_kernel(const float* __restrict__ x,
                const float* __restrict__ scale,
                const float* __restrict__ shift,
                float* __restrict__ out,
                int nrows)
{
    const int warp = (int)((blockIdx.x * blockDim.x + threadIdx.x) >> 5);
    const int lane = threadIdx.x & 31;
    if (warp >= nrows) return;

    const float4* __restrict__ xin  =
        reinterpret_cast<const float4*>(x + (size_t)warp * 1024u);
    float4* __restrict__ xout =
        reinterpret_cast<float4*>(out + (size_t)warp * 1024u);
    const float4* __restrict__ sc4 = reinterpret_cast<const float4*>(scale);
    const float4* __restrict__ sh4 = reinterpret_cast<const float4*>(shift);

    float4 a[8];
    // Coalesced streaming load: v = 32*k + lane
    #pragma unroll
    for (int k = 0; k < 8; k++)
        a[k] = __ldcs(&xin[k * 32 + lane]);

    // ---- stages on bits 0 and 1 (inside each float4) ----
    #pragma unroll
    for (int k = 0; k < 8; k++) {
        float4 t = a[k];
        float x0 = t.x + t.y;
        float y0 = t.x - t.y;
        float z0 = t.z + t.w;
        float w0 = t.z - t.w;
        a[k].x = x0 + z0;
        a[k].y = y0 + w0;
        a[k].z = x0 - z0;
        a[k].w = y0 - w0;
    }

    // ---- stages on bits 7,8,9 (register pairs k ^ m) ----
    #pragma unroll
    for (int m = 1; m < 8; m <<= 1) {
        #pragma unroll
        for (int k = 0; k < 8; k++) {
            if ((k & m) == 0) {
                float4 u = a[k];
                float4 v = a[k | m];
                a[k].x = u.x + v.x;  a[k | m].x = u.x - v.x;
                a[k].y = u.y + v.y;  a[k | m].y = u.y - v.y;
                a[k].z = u.z + v.z;  a[k | m].z = u.z - v.z;
                a[k].w = u.w + v.w;  a[k | m].w = u.w - v.w;
            }
        }
    }

    // ---- stages on bits 2..6 (lane butterflies via shfl_xor) ----
    #pragma unroll
    for (int mask = 1; mask <= 16; mask <<= 1) {
        const float sgn = (lane & mask) ? -1.0f : 1.0f;
        #pragma unroll
        for (int k = 0; k < 8; k++) {
            float ox = __shfl_xor_sync(FULL_MASK, a[k].x, mask);
            float oy = __shfl_xor_sync(FULL_MASK, a[k].y, mask);
            float oz = __shfl_xor_sync(FULL_MASK, a[k].z, mask);
            float ow = __shfl_xor_sync(FULL_MASK, a[k].w, mask);
            a[k].x = fmaf(sgn, a[k].x, ox);
            a[k].y = fmaf(sgn, a[k].y, oy);
            a[k].z = fmaf(sgn, a[k].z, oz);
            a[k].w = fmaf(sgn, a[k].w, ow);
        }
    }

    // ---- normalize (1/sqrt(1024) = 1/32), apply scale/shift, store ----
    const float inv = 0.03125f;
    #pragma unroll
    for (int k = 0; k < 8; k++) {
        const int v = k * 32 + lane;
        float4 sc = __ldg(&sc4[v]);
        float4 sh = __ldg(&sh4[v]);
        float4 r;
        r.x = fmaf(sc.x * inv, a[k].x, sh.x);
        r.y = fmaf(sc.y * inv, a[k].y, sh.y);
        r.z = fmaf(sc.z * inv, a[k].z, sh.z);
        r.w = fmaf(sc.w * inv, a[k].w, sh.w);
        __stcs(&xout[v], r);
    }
}

extern "C" void kernel_launch(void* const* d_in, const int* in_sizes, int n_in,
                              void* d_out, int out_size)
{
    const float* x     = (const float*)d_in[0];
    const float* scale = (const float*)d_in[1];
    const float* shift = (const float*)d_in[2];
    float* out = (float*)d_out;

    const int nrows = in_sizes[0] / 1024;          // 65536 for the bench shape
    const int warps_per_block = 8;                 // 256 threads
    const int blocks = (nrows + warps_per_block - 1) / warps_per_block;

    fwht1024_kernel<<<blocks, 256>>>(x, scale, shift, out, nrows);
}

// round 5
// speedup vs baseline: 1.1316x; 1.1316x over previous
#include <cuda_runtime.h>
#include <cstddef>

// One warp per row of 1024 floats, persistent grid-stride over rows.
// Thread owns 32 elements i = 128k + 4*lane + b, held as v[c], c = 4k+b.
//   c bits {0,1} = i bits {0,1};  c bits {2,3,4} = i bits {7,8,9}
// FWHT1024 = FWHT32 over c-bits  ∘  FWHT32 over lane-bits (i bits 2..6).
// The lane-bit half is done by a conflict-free 32x32 transpose (stride-33
// padded SMEM), a register FWHT32, and a transpose back. Zero shuffles.
// scale*(1/32) and shift are register-resident (loaded once per thread).

#define NWARPS 8

__global__ void __launch_bounds__(256, 2)
fwht1024_kernel(const float* __restrict__ x,
                const float* __restrict__ scale,
                const float* __restrict__ shift,
                float* __restrict__ out,
                int nrows, int warp_stride)
{
    __shared__ float xch[NWARPS][32 * 33];   // 4224 B per warp, 33.8 KB/block
    const int wlocal = threadIdx.x >> 5;
    const int lane   = threadIdx.x & 31;
    float* __restrict__ sm = xch[wlocal];

    // ---- preload scale*(1/sqrt(1024)) and shift for this thread's columns ----
    // column of v[4k+b] is 128k + 4*lane + b  ==  float4 index 32k+lane, comp b
    float sp[32], sb[32];
    const float4* __restrict__ sc4 = reinterpret_cast<const float4*>(scale);
    const float4* __restrict__ sh4 = reinterpret_cast<const float4*>(shift);
    const float inv = 0.03125f;
    #pragma unroll
    for (int k = 0; k < 8; k++) {
        float4 s4 = __ldg(&sc4[k * 32 + lane]);
        float4 h4 = __ldg(&sh4[k * 32 + lane]);
        sp[4*k+0] = s4.x * inv;  sp[4*k+1] = s4.y * inv;
        sp[4*k+2] = s4.z * inv;  sp[4*k+3] = s4.w * inv;
        sb[4*k+0] = h4.x;        sb[4*k+1] = h4.y;
        sb[4*k+2] = h4.z;        sb[4*k+3] = h4.w;
    }

    const int wid = blockIdx.x * NWARPS + wlocal;

    for (int row = wid; row < nrows; row += warp_stride) {
        const float4* __restrict__ xin =
            reinterpret_cast<const float4*>(x) + (size_t)row * 256u;
        float4* __restrict__ xo =
            reinterpret_cast<float4*>(out) + (size_t)row * 256u;

        float v[32];

        // coalesced streaming load: float4 index 32k+lane
        #pragma unroll
        for (int k = 0; k < 8; k++) {
            float4 t = __ldcs(&xin[k * 32 + lane]);
            v[4*k+0] = t.x; v[4*k+1] = t.y; v[4*k+2] = t.z; v[4*k+3] = t.w;
        }

        // ---- FWHT32 over register index (element bits 0,1,7,8,9) ----
        #pragma unroll
        for (int m = 1; m < 32; m <<= 1) {
            #pragma unroll
            for (int p = 0; p < 32; p++) {
                if ((p & m) == 0) {
                    float u = v[p], w = v[p | m];
                    v[p]     = u + w;
                    v[p | m] = u - w;
                }
            }
        }

        // ---- transpose: sm[lane*33+c] write (banks lane+c: CF),
        //                 sm[j*33+lane]  read  (consecutive: CF) ----
        #pragma unroll
        for (int c = 0; c < 32; c++) sm[lane * 33 + c] = v[c];
        __syncwarp();
        #pragma unroll
        for (int j = 0; j < 32; j++) v[j] = sm[j * 33 + lane];

        // ---- FWHT32 over new register index (element bits 2..6) ----
        #pragma unroll
        for (int m = 1; m < 32; m <<= 1) {
            #pragma unroll
            for (int p = 0; p < 32; p++) {
                if ((p & m) == 0) {
                    float u = v[p], w = v[p | m];
                    v[p]     = u + w;
                    v[p | m] = u - w;
                }
            }
        }

        // ---- transpose back (same addresses, roles swapped) ----
        // write sm[j*33+lane] overwrites only words this thread just read: no sync needed before
        #pragma unroll
        for (int j = 0; j < 32; j++) sm[j * 33 + lane] = v[j];
        __syncwarp();
        #pragma unroll
        for (int c = 0; c < 32; c++) v[c] = sm[lane * 33 + c];

        // ---- epilogue: scale/shift, coalesced streaming store ----
        #pragma unroll
        for (int k = 0; k < 8; k++) {
            float4 r;
            r.x = fmaf(sp[4*k+0], v[4*k+0], sb[4*k+0]);
            r.y = fmaf(sp[4*k+1], v[4*k+1], sb[4*k+1]);
            r.z = fmaf(sp[4*k+2], v[4*k+2], sb[4*k+2]);
            r.w = fmaf(sp[4*k+3], v[4*k+3], sb[4*k+3]);
            __stcs(&xo[k * 32 + lane], r);
        }
        // next-iter transpose writes touch only words this thread last read: safe
    }
}

extern "C" void kernel_launch(void* const* d_in, const int* in_sizes, int n_in,
                              void* d_out, int out_size)
{
    const float* x     = (const float*)d_in[0];
    const float* scale = (const float*)d_in[1];
    const float* shift = (const float*)d_in[2];
    float* out = (float*)d_out;

    const int nrows = in_sizes[0] / 1024;

    int sms = 148;
    cudaDeviceGetAttribute(&sms, cudaDevAttrMultiProcessorCount, 0);
    const int blocks = sms * 2;                 // 2 CTAs/SM (smem + regs fit)
    const int warp_stride = blocks * NWARPS;    // persistent grid-stride

    fwht1024_kernel<<<blocks, 32 * NWARPS>>>(x, scale, shift, out,
                                             nrows, warp_stride);
}